// round 15
// baseline (speedup 1.0000x reference)
#include <cuda_runtime.h>
#include <math.h>

#define D 16
#define EF 8
#define NLAYERS 3
#define MAX_N 50048
#define MAX_E 500224
#define SCB 128
#define FP_SCALE 4294967296.0f
#define FP_INVF 2.3283064365386963e-10f
#define FP_INV 2.3283064365386963e-10
#define GMSG_BLOCKS 740              // persistent grid: 5 blocks x 148 SMs
#define AGG_BLOCKS 592               // persistent grid: 4 blocks x 148 SMs (co-resident)

// ---------------- static device scratch ----------------
struct ZeroBlk {                             // zeroed by ONE cudaMemsetAsync
    unsigned long long acc[MAX_N * D];       // int64 fixed-point message accumulators
    int deg[2][MAX_N];                       // 0=src deg, 1=dst deg
    int cur[MAX_N];                          // src-CSR fill cursor
    int aggctr[NLAYERS];                     // K_aggbn barrier counters
};
__device__ ZeroBlk g_z;

__device__ float g_he_s[MAX_E * D];          // edge MLP output, src-CSR order
__device__ int   g_dn  [MAX_E];              // src-slot -> dst NODE id
__device__ int   g_off [MAX_N + 1];          // src-CSR offsets (monotonic)
__device__ int   g_part[SCB];                // scan partials
__device__ float g_hbuf[MAX_N * D];          // activated features (layer input)
__device__ float g_hpre[MAX_N * D];          // pre-BN activations
__device__ unsigned long long g_bnsum[32];   // fixed-point BN sum / sumsq

// fast tanh (EX2 + fast divide), err ~1e-7
__device__ __forceinline__ float ftanh(float x) {
    x = fminf(fmaxf(x, -15.f), 15.f);
    float e = __expf(2.f * x);
    return __fdividef(e - 1.f, e + 1.f);
}

// block exclusive scan of one int per thread; total left in s_w[32]
__device__ __forceinline__ int blk_ex_scan(int v, int* s_w) {
    int tid = threadIdx.x, lane = tid & 31, wid = tid >> 5;
    int nw = blockDim.x >> 5;
    int x = v;
#pragma unroll
    for (int d = 1; d < 32; d <<= 1) {
        int y = __shfl_up_sync(0xffffffffu, x, d);
        if (lane >= d) x += y;
    }
    if (lane == 31) s_w[wid] = x;
    __syncthreads();
    if (wid == 0) {
        int w = (lane < nw) ? s_w[lane] : 0;
        int xw = w;
#pragma unroll
        for (int d = 1; d < 32; d <<= 1) {
            int y = __shfl_up_sync(0xffffffffu, xw, d);
            if (lane >= d) xw += y;
        }
        if (lane < nw) s_w[lane] = xw - w;
        if (lane == 31) s_w[32] = xw;
    }
    __syncthreads();
    return s_w[wid] + (x - v);
}

// ---------------- K_deg ----------------
__global__ void K_deg(const int* __restrict__ ei, int E) {
    int e = blockIdx.x * blockDim.x + threadIdx.x;
    if (e >= E) return;
    atomicAdd(&g_z.deg[0][ei[e]], 1);
    atomicAdd(&g_z.deg[1][ei[E + e]], 1);
}

// ---------------- K_s1: per-block partial sums over src degrees --------------
__global__ void K_s1(int n) {
    int chunk = (n + SCB - 1) / SCB;
    int beg = blockIdx.x * chunk;
    int end = min(n, beg + chunk);
    int s = 0;
    for (int i = beg + threadIdx.x; i < end; i += blockDim.x) s += g_z.deg[0][i];
    __shared__ int sw[8];
    int lane = threadIdx.x & 31, wid = threadIdx.x >> 5;
#pragma unroll
    for (int o = 16; o; o >>= 1) s += __shfl_down_sync(0xffffffffu, s, o);
    if (lane == 0) sw[wid] = s;
    __syncthreads();
    if (threadIdx.x == 0) {
        int t = 0;
        for (int w = 0; w < (int)(blockDim.x >> 5); w++) t += sw[w];
        g_part[blockIdx.x] = t;
    }
}

// ---------------- K_s3: fused partial-scan + apply ----------------
__global__ void K_s3(int n) {
    __shared__ int s_w[33];
    __shared__ int sred[8];
    __shared__ int s_base;
    {
        int v = (threadIdx.x < SCB && threadIdx.x < (int)blockIdx.x) ? g_part[threadIdx.x] : 0;
        int lane = threadIdx.x & 31, wid = threadIdx.x >> 5;
#pragma unroll
        for (int d2 = 16; d2; d2 >>= 1) v += __shfl_down_sync(0xffffffffu, v, d2);
        if (lane == 0) sred[wid] = v;
        __syncthreads();
        if (threadIdx.x == 0) {
            int t = 0;
            for (int w = 0; w < 8; w++) t += sred[w];
            s_base = t;
        }
        __syncthreads();
    }
    int chunk = (n + SCB - 1) / SCB;
    int beg = blockIdx.x * chunk;
    int end = min(n, beg + chunk);
    int base = s_base;
    for (int t0 = beg; t0 < end; t0 += blockDim.x) {
        int i = t0 + threadIdx.x;
        int v = (i < end) ? g_z.deg[0][i] : 0;
        int ex = blk_ex_scan(v, s_w);
        int tot = s_w[32];
        __syncthreads();
        if (i < end) g_off[i] = base + ex;
        base += tot;
    }
    if (blockIdx.x == SCB - 1 && threadIdx.x == 0) g_off[n] = base;
}

// ---------------- K_edgefill: edge MLP -> src-CSR slot + dst node id ---------
__global__ void K_edgefill(const float* __restrict__ edge_attr,
                           const float* __restrict__ w1,
                           const float* __restrict__ b1,
                           const int*   __restrict__ ei, int E) {
    __shared__ float s_w1[EF * D];
    __shared__ float s_b1[D];
    int tid = threadIdx.x;
    if (tid < EF * D) s_w1[tid] = w1[tid];
    if (tid < D)      s_b1[tid] = b1[tid];
    __syncthreads();

    int e = blockIdx.x * blockDim.x + tid;
    if (e >= E) return;

    const float4* ea = (const float4*)(edge_attr + (size_t)e * EF);
    float4 a0 = ea[0], a1 = ea[1];
    float a[8] = {a0.x, a0.y, a0.z, a0.w, a1.x, a1.y, a1.z, a1.w};

    float out[D];
#pragma unroll
    for (int j = 0; j < D; j++) {
        float acc = s_b1[j];
#pragma unroll
        for (int k = 0; k < EF; k++) acc += a[k] * s_w1[k * D + j];
        out[j] = ftanh(acc);
    }

    int s = ei[e];
    int d = ei[E + e];
    int ps = g_off[s] + atomicAdd(&g_z.cur[s], 1);
    g_dn[ps] = d;
    float4* dst4 = (float4*)(g_he_s + (size_t)ps * D);
    dst4[0] = make_float4(out[0], out[1], out[2], out[3]);
    dst4[1] = make_float4(out[4], out[5], out[6], out[7]);
    dst4[2] = make_float4(out[8], out[9], out[10], out[11]);
    dst4[3] = make_float4(out[12], out[13], out[14], out[15]);
}

// ---------------- K_gmsg: persistent fused transform + message scatter -------
// (champion structure, unchanged)
__global__ void __launch_bounds__(256) K_gmsg(const float* __restrict__ h_in,
                                              const float* __restrict__ w2,
                                              const float* __restrict__ b2,
                                              int N, int nodeBlocks) {
    __shared__ float s_w2[D * 256];
    __shared__ float s_b2[256];
    int tid = threadIdx.x;
    for (int i = tid; i < D * 256; i += blockDim.x) s_w2[i] = w2[i];
    for (int i = tid; i < 256; i += blockDim.x)     s_b2[i] = b2[i];
    if (blockIdx.x == 0 && tid < 32) g_bnsum[tid] = 0ull;  // reset BN accum
    __syncthreads();

    int o = tid & 15;

    for (int nb = blockIdx.x; nb < nodeBlocks; nb += gridDim.x) {
        int node = nb * 16 + (tid >> 4);
        if (node >= N) continue;

        float hv[D];
        {
            const float4* h4 = (const float4*)(h_in + (size_t)node * D);
            float4 v;
            v = h4[0]; hv[0]=v.x; hv[1]=v.y; hv[2]=v.z; hv[3]=v.w;
            v = h4[1]; hv[4]=v.x; hv[5]=v.y; hv[6]=v.z; hv[7]=v.w;
            v = h4[2]; hv[8]=v.x; hv[9]=v.y; hv[10]=v.z; hv[11]=v.w;
            v = h4[3]; hv[12]=v.x; hv[13]=v.y; hv[14]=v.z; hv[15]=v.w;
        }

        float ga[D];
#pragma unroll
        for (int j = 0; j < D; j++) ga[j] = 0.f;
        float btv = 0.f;
#pragma unroll
        for (int i = 0; i < D; i++) {
            float h = hv[i];
            int base = i * D + o;
#pragma unroll
            for (int j = 0; j < D; j++) ga[j] += h * s_w2[j * 256 + base];
            btv += h * s_b2[base];
        }

        int beg = g_off[node];
        int end = g_off[node + 1];
        int ps = beg;
        for (; ps + 4 <= end; ps += 4) {
            const float4* b4 = (const float4*)(g_he_s + (size_t)ps * D);
            float4 r0 = b4[0],  r1 = b4[1],  r2 = b4[2],  r3 = b4[3];
            float4 r4 = b4[4],  r5 = b4[5],  r6 = b4[6],  r7 = b4[7];
            float4 r8 = b4[8],  r9 = b4[9],  rA = b4[10], rB = b4[11];
            float4 rC = b4[12], rD = b4[13], rE = b4[14], rF = b4[15];
            int d0 = g_dn[ps], d1 = g_dn[ps+1], d2 = g_dn[ps+2], d3 = g_dn[ps+3];

            float m0 = btv, m1 = btv, m2 = btv, m3 = btv;
            m0 += r0.x*ga[0]+r0.y*ga[1]+r0.z*ga[2]+r0.w*ga[3]
                + r1.x*ga[4]+r1.y*ga[5]+r1.z*ga[6]+r1.w*ga[7]
                + r2.x*ga[8]+r2.y*ga[9]+r2.z*ga[10]+r2.w*ga[11]
                + r3.x*ga[12]+r3.y*ga[13]+r3.z*ga[14]+r3.w*ga[15];
            m1 += r4.x*ga[0]+r4.y*ga[1]+r4.z*ga[2]+r4.w*ga[3]
                + r5.x*ga[4]+r5.y*ga[5]+r5.z*ga[6]+r5.w*ga[7]
                + r6.x*ga[8]+r6.y*ga[9]+r6.z*ga[10]+r6.w*ga[11]
                + r7.x*ga[12]+r7.y*ga[13]+r7.z*ga[14]+r7.w*ga[15];
            m2 += r8.x*ga[0]+r8.y*ga[1]+r8.z*ga[2]+r8.w*ga[3]
                + r9.x*ga[4]+r9.y*ga[5]+r9.z*ga[6]+r9.w*ga[7]
                + rA.x*ga[8]+rA.y*ga[9]+rA.z*ga[10]+rA.w*ga[11]
                + rB.x*ga[12]+rB.y*ga[13]+rB.z*ga[14]+rB.w*ga[15];
            m3 += rC.x*ga[0]+rC.y*ga[1]+rC.z*ga[2]+rC.w*ga[3]
                + rD.x*ga[4]+rD.y*ga[5]+rD.z*ga[6]+rD.w*ga[7]
                + rE.x*ga[8]+rE.y*ga[9]+rE.z*ga[10]+rE.w*ga[11]
                + rF.x*ga[12]+rF.y*ga[13]+rF.z*ga[14]+rF.w*ga[15];

            atomicAdd(&g_z.acc[(size_t)d0 * D + o], (unsigned long long)(long long)llrintf(m0 * FP_SCALE));
            atomicAdd(&g_z.acc[(size_t)d1 * D + o], (unsigned long long)(long long)llrintf(m1 * FP_SCALE));
            atomicAdd(&g_z.acc[(size_t)d2 * D + o], (unsigned long long)(long long)llrintf(m2 * FP_SCALE));
            atomicAdd(&g_z.acc[(size_t)d3 * D + o], (unsigned long long)(long long)llrintf(m3 * FP_SCALE));
        }
        for (; ps < end; ps++) {
            const float4* he4 = (const float4*)(g_he_s + (size_t)ps * D);
            float4 h0 = he4[0], h1 = he4[1], h2 = he4[2], h3 = he4[3];
            float m = btv;
            m += h0.x*ga[0]  + h0.y*ga[1]  + h0.z*ga[2]  + h0.w*ga[3];
            m += h1.x*ga[4]  + h1.y*ga[5]  + h1.z*ga[6]  + h1.w*ga[7];
            m += h2.x*ga[8]  + h2.y*ga[9]  + h2.z*ga[10] + h2.w*ga[11];
            m += h3.x*ga[12] + h3.y*ga[13] + h3.z*ga[14] + h3.w*ga[15];
            atomicAdd(&g_z.acc[(size_t)g_dn[ps] * D + o], (unsigned long long)(long long)llrintf(m * FP_SCALE));
        }
    }
}

// ---------------- K_aggbn: aggregate + root + BN stats [+ barrier + BN apply]
// Persistent grid (<= 4 blocks/SM guaranteed co-resident). apply=1: after all
// blocks finish stats, device-wide counter barrier, then BN+tanh -> h_out.
__global__ void __launch_bounds__(256, 4) K_aggbn(const float* __restrict__ h_in,
                                                  const float* __restrict__ root,
                                                  const float* __restrict__ conv_bias,
                                                  const float* __restrict__ gamma,
                                                  const float* __restrict__ beta,
                                                  float* __restrict__ h_out,
                                                  int layer, int apply,
                                                  int N, int chunks) {
    __shared__ float s_root[D * D];
    __shared__ float s_bias[D];
    __shared__ unsigned long long s_sum[D];
    __shared__ unsigned long long s_sq[D];
    __shared__ float s_sc[D], s_sh[D];
    int tid = threadIdx.x;
    if (tid < D * D) s_root[tid] = root[layer * D * D + tid];
    if (tid < D)     s_bias[tid] = conv_bias[layer * D + tid];
    if (tid < D)     { s_sum[tid] = 0ull; s_sq[tid] = 0ull; }
    __syncthreads();

    int o = tid & 15;

    // ---- part 1: aggregate + root term + local BN stats ----
    for (int c = blockIdx.x; c < chunks; c += gridDim.x) {
        int gi = c * 256 + tid;
        int n = gi >> 4;
        if (n >= N) continue;

        long long acc = (long long)g_z.acc[gi];
        g_z.acc[gi] = 0ull;                      // re-arm for next layer
        float aggv = (float)(int)(acc >> 32) + (float)(unsigned)acc * FP_INVF;
        int deg = g_z.deg[1][n];
        if (deg == 0) deg = 1;
        aggv = __fdividef(aggv, (float)deg);

        float hv[D];
        const float4* h4 = (const float4*)(h_in + (size_t)n * D);
        float4 v4;
        v4 = h4[0]; hv[0]=v4.x; hv[1]=v4.y; hv[2]=v4.z; hv[3]=v4.w;
        v4 = h4[1]; hv[4]=v4.x; hv[5]=v4.y; hv[6]=v4.z; hv[7]=v4.w;
        v4 = h4[2]; hv[8]=v4.x; hv[9]=v4.y; hv[10]=v4.z; hv[11]=v4.w;
        v4 = h4[3]; hv[12]=v4.x; hv[13]=v4.y; hv[14]=v4.z; hv[15]=v4.w;

        float hs = aggv + s_bias[o];
#pragma unroll
        for (int i = 0; i < D; i++) hs += hv[i] * s_root[i * D + o];

        g_hpre[gi] = hs;
        atomicAdd(&s_sum[o], (unsigned long long)(long long)llrintf(hs * FP_SCALE));
        atomicAdd(&s_sq[o],  (unsigned long long)(long long)llrintf(hs * hs * FP_SCALE));
    }
    __syncthreads();
    if (tid < D) {
        atomicAdd(&g_bnsum[tid],     s_sum[tid]);
        atomicAdd(&g_bnsum[D + tid], s_sq[tid]);
    }
    if (!apply) return;

    // ---- device-wide barrier (all gridDim.x blocks co-resident) ----
    __syncthreads();
    if (tid == 0) {
        __threadfence();
        atomicAdd(&g_z.aggctr[layer], 1);
        while (atomicAdd(&g_z.aggctr[layer], 0) < (int)gridDim.x) {}
    }
    __syncthreads();

    // ---- part 2: BN coefficients + apply tanh ----
    if (tid < D) {
        long long ssum = (long long)atomicAdd(&g_bnsum[tid],     0ull);
        long long ssq  = (long long)atomicAdd(&g_bnsum[D + tid], 0ull);
        double sum = (double)ssum * FP_INV;
        double sq  = (double)ssq  * FP_INV;
        double inv = 1.0 / (double)N;
        double mu  = sum * inv;
        double var = sq * inv - mu * mu;
        float sc = gamma[layer * D + tid] * rsqrtf((float)(var + 1e-5));
        s_sc[tid] = sc;
        s_sh[tid] = beta[layer * D + tid] - (float)mu * sc;
    }
    __syncthreads();
    for (int c = blockIdx.x; c < chunks; c += gridDim.x) {
        int gi = c * 256 + tid;
        if ((gi >> 4) >= N) continue;
        h_out[gi] = ftanh(g_hpre[gi] * s_sc[o] + s_sh[o]);
    }
}

// ---------------- K_poolfc: final BN+tanh + hidden out + pooling + MLP -------
__global__ void K_poolfc(const int*   __restrict__ lengths,
                         const float* __restrict__ gamma, const float* __restrict__ beta,
                         const float* __restrict__ fc1_w, const float* __restrict__ fc1_b,
                         const float* __restrict__ fc2_w, const float* __restrict__ fc2_b,
                         float* __restrict__ hidden_out, float* __restrict__ pooled,
                         float* __restrict__ fc_out, float* __restrict__ ls_out,
                         int N, int G) {
    int g = blockIdx.x, t = threadIdx.x;   // 128 threads
    __shared__ float shs[128], shx[128], shn[128];
    __shared__ int swi[4];
    __shared__ int s_nb;
    __shared__ float sp[64], st16[16], sfc[16];
    __shared__ float s_lse;
    __shared__ float s_sc[D], s_sh[D];

    // BN coefficients for the final layer (stats complete: stream-ordered)
    if (t < D) {
        double sum = (double)(long long)g_bnsum[t]     * FP_INV;
        double sq  = (double)(long long)g_bnsum[D + t] * FP_INV;
        double inv = 1.0 / (double)N;
        double mu  = sum * inv;
        double var = sq * inv - mu * mu;
        float sc = gamma[(NLAYERS - 1) * D + t] * rsqrtf((float)(var + 1e-5));
        s_sc[t] = sc;
        s_sh[t] = beta[(NLAYERS - 1) * D + t] - (float)mu * sc;
    }

    int acc = 0;
    for (int i = t; i < g; i += 128) acc += lengths[i];
#pragma unroll
    for (int off = 16; off; off >>= 1) acc += __shfl_down_sync(0xffffffffu, acc, off);
    if ((t & 31) == 0) swi[t >> 5] = acc;
    __syncthreads();
    if (t == 0) s_nb = swi[0] + swi[1] + swi[2] + swi[3];
    __syncthreads();
    int nb = s_nb;
    int len = lengths[g];
    int ne = min(N, nb + len);

    int c = t & 15, r = t >> 4;
    float scl = s_sc[c], shf = s_sh[c];
    float s = 0.f, mx = -3.402823e38f, mn = 3.402823e38f;
    for (int i = nb + r; i < ne; i += 8) {
        float v = ftanh(g_hpre[i * D + c] * scl + shf);
        hidden_out[i * D + c] = v;
        s += v; mx = fmaxf(mx, v); mn = fminf(mn, v);
    }
    shs[t] = s; shx[t] = mx; shn[t] = mn;
    __syncthreads();
    for (int off = 64; off >= 16; off >>= 1) {
        if (t < off) {
            shs[t] += shs[t + off];
            shx[t] = fmaxf(shx[t], shx[t + off]);
            shn[t] = fminf(shn[t], shn[t + off]);
        }
        __syncthreads();
    }
    if (t < D) {
        float cnt = fmaxf((float)len, 1.f);
        float ssum = shs[t];
        sp[t]      = __fdividef(ssum, cnt);
        sp[16 + t] = shx[t];
        sp[32 + t] = shn[t];
        sp[48 + t] = ssum;
        pooled[g * 64 + t]      = sp[t];
        pooled[g * 64 + 16 + t] = shx[t];
        pooled[g * 64 + 32 + t] = shn[t];
        pooled[g * 64 + 48 + t] = ssum;
    }
    __syncthreads();
    if (t < 16) {
        float a = fc1_b[t];
#pragma unroll
        for (int k = 0; k < 64; k++) a += sp[k] * fc1_w[k * 16 + t];
        st16[t] = ftanh(a);
    }
    __syncthreads();
    if (t < 10) {
        float a = fc2_b[t];
#pragma unroll
        for (int k = 0; k < 16; k++) a += st16[k] * fc2_w[k * 10 + t];
        sfc[t] = a;
        fc_out[g * 10 + t] = a;
    }
    __syncthreads();
    if (t == 0) {
        float m = sfc[0];
        for (int k = 1; k < 10; k++) m = fmaxf(m, sfc[k]);
        float se = 0.f;
        for (int k = 0; k < 10; k++) se += __expf(sfc[k] - m);
        s_lse = __logf(se) + m;
    }
    __syncthreads();
    if (t < 10) ls_out[g * 10 + t] = sfc[t] - s_lse;
}

// =============================== host launcher =================================
extern "C" void kernel_launch(void* const* d_in, const int* in_sizes, int n_in,
                              void* d_out, int out_size) {
    const float* x         = (const float*)d_in[0];
    const float* edge_attr = (const float*)d_in[1];
    const float* edge_w1   = (const float*)d_in[2];
    const float* edge_b1   = (const float*)d_in[3];
    const float* edge_w2   = (const float*)d_in[4];
    const float* edge_b2   = (const float*)d_in[5];
    const float* root      = (const float*)d_in[6];
    const float* conv_bias = (const float*)d_in[7];
    const float* bn_gamma  = (const float*)d_in[8];
    const float* bn_beta   = (const float*)d_in[9];
    const float* fc1_w     = (const float*)d_in[10];
    const float* fc1_b     = (const float*)d_in[11];
    const float* fc2_w     = (const float*)d_in[12];
    const float* fc2_b     = (const float*)d_in[13];
    const int*   edge_index= (const int*)d_in[14];
    const int*   lengths   = (const int*)d_in[15];

    int N = in_sizes[0] / D;
    int E = in_sizes[1] / EF;
    int G = in_sizes[15];

    float* out        = (float*)d_out;
    float* out_hidden = out;
    float* out_pooled = out + (size_t)N * D;
    float* out_fc     = out_pooled + (size_t)G * 64;
    float* out_ls     = out_fc + (size_t)G * 10;

    // ---- setup: one memset, degrees, fused CSR scan, edge MLP fill ----
    void* zp = 0;
    cudaGetSymbolAddress(&zp, g_z);
    cudaMemsetAsync(zp, 0, sizeof(ZeroBlk));

    K_deg <<<(E + 255) / 256, 256>>>(edge_index, E);
    K_s1  <<<SCB, 256>>>(N);
    K_s3  <<<SCB, 256>>>(N);
    K_edgefill<<<(E + 127) / 128, 128>>>(edge_attr, edge_w1, edge_b1, edge_index, E);

    int nodeBlocks = (N + 15) / 16;
    int chunks = (N * D + 255) / 256;
    int gmsgGrid = GMSG_BLOCKS < nodeBlocks ? GMSG_BLOCKS : nodeBlocks;
    int aggGrid  = AGG_BLOCKS < chunks ? AGG_BLOCKS : chunks;

    // ---- layers ----
    for (int l = 0; l < NLAYERS; l++) {
        const float* h_in = (l == 0) ? x : g_hbuf;
        int apply = (l < NLAYERS - 1);           // last layer: poolfc applies BN
        K_gmsg <<<gmsgGrid, 256>>>(h_in, edge_w2, edge_b2, N, nodeBlocks);
        K_aggbn<<<aggGrid, 256>>>(h_in, root, conv_bias, bn_gamma, bn_beta,
                                  g_hbuf, l, apply, N, chunks);
    }

    // ---- final BN + hidden + pooling + readout ----
    K_poolfc<<<G, 128>>>(lengths, bn_gamma, bn_beta, fc1_w, fc1_b, fc2_w, fc2_b,
                         out_hidden, out_pooled, out_fc, out_ls, N, G);
}

// round 16
// speedup vs baseline: 1.0656x; 1.0656x over previous
#include <cuda_runtime.h>
#include <math.h>

#define D 16
#define EF 8
#define NLAYERS 3
#define MAX_N 50048
#define MAX_E 500224
#define SCB 128
#define FP_SCALE 4294967296.0f
#define FP_INVF 2.3283064365386963e-10f
#define FP_INV 2.3283064365386963e-10
#define GMSG_BLOCKS 740              // persistent grid: 5 blocks x 148 SMs

// ---------------- static device scratch ----------------
struct ZeroBlk {                             // zeroed by ONE small cudaMemsetAsync
    int deg[2][MAX_N];                       // 0=src deg, 1=dst deg
    int cur[MAX_N];                          // src-CSR fill cursor
};
__device__ ZeroBlk g_z;

// acc is NOT in the memset: zero-initialized at module load, and K_agg re-arms
// every word to 0 after reading it, so it is zero at entry of every launch.
__device__ unsigned long long g_acc[MAX_N * D];

__device__ float g_he_s[MAX_E * D];          // edge MLP output, src-CSR order
__device__ int   g_dn  [MAX_E];              // src-slot -> dst NODE id
__device__ int   g_off [MAX_N + 1];          // src-CSR offsets (monotonic)
__device__ int   g_part[SCB];                // scan partials
__device__ float g_hbuf[MAX_N * D];          // activated features (layer input)
__device__ float g_hpre[MAX_N * D];          // pre-BN activations
__device__ unsigned long long g_bnsum[32];   // fixed-point BN sum / sumsq

// fast tanh (EX2 + fast divide), err ~1e-7
__device__ __forceinline__ float ftanh(float x) {
    x = fminf(fmaxf(x, -15.f), 15.f);
    float e = __expf(2.f * x);
    return __fdividef(e - 1.f, e + 1.f);
}

// block exclusive scan of one int per thread; total left in s_w[32]
__device__ __forceinline__ int blk_ex_scan(int v, int* s_w) {
    int tid = threadIdx.x, lane = tid & 31, wid = tid >> 5;
    int nw = blockDim.x >> 5;
    int x = v;
#pragma unroll
    for (int d = 1; d < 32; d <<= 1) {
        int y = __shfl_up_sync(0xffffffffu, x, d);
        if (lane >= d) x += y;
    }
    if (lane == 31) s_w[wid] = x;
    __syncthreads();
    if (wid == 0) {
        int w = (lane < nw) ? s_w[lane] : 0;
        int xw = w;
#pragma unroll
        for (int d = 1; d < 32; d <<= 1) {
            int y = __shfl_up_sync(0xffffffffu, xw, d);
            if (lane >= d) xw += y;
        }
        if (lane < nw) s_w[lane] = xw - w;
        if (lane == 31) s_w[32] = xw;
    }
    __syncthreads();
    return s_w[wid] + (x - v);
}

// ---------------- K_deg ----------------
__global__ void K_deg(const int* __restrict__ ei, int E) {
    int e = blockIdx.x * blockDim.x + threadIdx.x;
    if (e >= E) return;
    atomicAdd(&g_z.deg[0][ei[e]], 1);
    atomicAdd(&g_z.deg[1][ei[E + e]], 1);
}

// ---------------- K_s1: per-block partial sums over src degrees --------------
__global__ void K_s1(int n) {
    int chunk = (n + SCB - 1) / SCB;
    int beg = blockIdx.x * chunk;
    int end = min(n, beg + chunk);
    int s = 0;
    for (int i = beg + threadIdx.x; i < end; i += blockDim.x) s += g_z.deg[0][i];
    __shared__ int sw[8];
    int lane = threadIdx.x & 31, wid = threadIdx.x >> 5;
#pragma unroll
    for (int o = 16; o; o >>= 1) s += __shfl_down_sync(0xffffffffu, s, o);
    if (lane == 0) sw[wid] = s;
    __syncthreads();
    if (threadIdx.x == 0) {
        int t = 0;
        for (int w = 0; w < (int)(blockDim.x >> 5); w++) t += sw[w];
        g_part[blockIdx.x] = t;
    }
}

// ---------------- K_s3: fused partial-scan + apply ----------------
__global__ void K_s3(int n) {
    __shared__ int s_w[33];
    __shared__ int sred[8];
    __shared__ int s_base;
    {
        int v = (threadIdx.x < SCB && threadIdx.x < (int)blockIdx.x) ? g_part[threadIdx.x] : 0;
        int lane = threadIdx.x & 31, wid = threadIdx.x >> 5;
#pragma unroll
        for (int d2 = 16; d2; d2 >>= 1) v += __shfl_down_sync(0xffffffffu, v, d2);
        if (lane == 0) sred[wid] = v;
        __syncthreads();
        if (threadIdx.x == 0) {
            int t = 0;
            for (int w = 0; w < 8; w++) t += sred[w];
            s_base = t;
        }
        __syncthreads();
    }
    int chunk = (n + SCB - 1) / SCB;
    int beg = blockIdx.x * chunk;
    int end = min(n, beg + chunk);
    int base = s_base;
    for (int t0 = beg; t0 < end; t0 += blockDim.x) {
        int i = t0 + threadIdx.x;
        int v = (i < end) ? g_z.deg[0][i] : 0;
        int ex = blk_ex_scan(v, s_w);
        int tot = s_w[32];
        __syncthreads();
        if (i < end) g_off[i] = base + ex;
        base += tot;
    }
    if (blockIdx.x == SCB - 1 && threadIdx.x == 0) g_off[n] = base;
}

// ---------------- K_edgefill: edge MLP -> src-CSR slot + dst node id ---------
__global__ void K_edgefill(const float* __restrict__ edge_attr,
                           const float* __restrict__ w1,
                           const float* __restrict__ b1,
                           const int*   __restrict__ ei, int E) {
    __shared__ float s_w1[EF * D];
    __shared__ float s_b1[D];
    int tid = threadIdx.x;
    if (tid < EF * D) s_w1[tid] = w1[tid];
    if (tid < D)      s_b1[tid] = b1[tid];
    __syncthreads();

    int e = blockIdx.x * blockDim.x + tid;
    if (e >= E) return;

    const float4* ea = (const float4*)(edge_attr + (size_t)e * EF);
    float4 a0 = ea[0], a1 = ea[1];
    float a[8] = {a0.x, a0.y, a0.z, a0.w, a1.x, a1.y, a1.z, a1.w};

    float out[D];
#pragma unroll
    for (int j = 0; j < D; j++) {
        float acc = s_b1[j];
#pragma unroll
        for (int k = 0; k < EF; k++) acc += a[k] * s_w1[k * D + j];
        out[j] = ftanh(acc);
    }

    int s = ei[e];
    int d = ei[E + e];
    int ps = g_off[s] + atomicAdd(&g_z.cur[s], 1);
    g_dn[ps] = d;
    float4* dst4 = (float4*)(g_he_s + (size_t)ps * D);
    dst4[0] = make_float4(out[0], out[1], out[2], out[3]);
    dst4[1] = make_float4(out[4], out[5], out[6], out[7]);
    dst4[2] = make_float4(out[8], out[9], out[10], out[11]);
    dst4[3] = make_float4(out[12], out[13], out[14], out[15]);
}

// ---------------- K_gmsg: persistent fused transform + message scatter -------
// Half-warp per node, lane o. Transform in registers; messages REDG.64'd into
// g_acc (order-invariant int64 fixed point). Grid-stride over node blocks.
__global__ void __launch_bounds__(256) K_gmsg(const float* __restrict__ h_in,
                                              const float* __restrict__ w2,
                                              const float* __restrict__ b2,
                                              int N, int nodeBlocks) {
    __shared__ float s_w2[D * 256];
    __shared__ float s_b2[256];
    int tid = threadIdx.x;
    for (int i = tid; i < D * 256; i += blockDim.x) s_w2[i] = w2[i];
    for (int i = tid; i < 256; i += blockDim.x)     s_b2[i] = b2[i];
    if (blockIdx.x == 0 && tid < 32) g_bnsum[tid] = 0ull;  // reset BN accum
    __syncthreads();

    int o = tid & 15;

    for (int nb = blockIdx.x; nb < nodeBlocks; nb += gridDim.x) {
        int node = nb * 16 + (tid >> 4);
        if (node >= N) continue;

        float hv[D];
        {
            const float4* h4 = (const float4*)(h_in + (size_t)node * D);
            float4 v;
            v = h4[0]; hv[0]=v.x; hv[1]=v.y; hv[2]=v.z; hv[3]=v.w;
            v = h4[1]; hv[4]=v.x; hv[5]=v.y; hv[6]=v.z; hv[7]=v.w;
            v = h4[2]; hv[8]=v.x; hv[9]=v.y; hv[10]=v.z; hv[11]=v.w;
            v = h4[3]; hv[12]=v.x; hv[13]=v.y; hv[14]=v.z; hv[15]=v.w;
        }

        float ga[D];
#pragma unroll
        for (int j = 0; j < D; j++) ga[j] = 0.f;
        float btv = 0.f;
#pragma unroll
        for (int i = 0; i < D; i++) {
            float h = hv[i];
            int base = i * D + o;
#pragma unroll
            for (int j = 0; j < D; j++) ga[j] += h * s_w2[j * 256 + base];
            btv += h * s_b2[base];
        }

        int beg = g_off[node];
        int end = g_off[node + 1];
        int ps = beg;
        for (; ps + 4 <= end; ps += 4) {
            const float4* b4 = (const float4*)(g_he_s + (size_t)ps * D);
            float4 r0 = b4[0],  r1 = b4[1],  r2 = b4[2],  r3 = b4[3];
            float4 r4 = b4[4],  r5 = b4[5],  r6 = b4[6],  r7 = b4[7];
            float4 r8 = b4[8],  r9 = b4[9],  rA = b4[10], rB = b4[11];
            float4 rC = b4[12], rD = b4[13], rE = b4[14], rF = b4[15];
            int d0 = g_dn[ps], d1 = g_dn[ps+1], d2 = g_dn[ps+2], d3 = g_dn[ps+3];

            float m0 = btv, m1 = btv, m2 = btv, m3 = btv;
            m0 += r0.x*ga[0]+r0.y*ga[1]+r0.z*ga[2]+r0.w*ga[3]
                + r1.x*ga[4]+r1.y*ga[5]+r1.z*ga[6]+r1.w*ga[7]
                + r2.x*ga[8]+r2.y*ga[9]+r2.z*ga[10]+r2.w*ga[11]
                + r3.x*ga[12]+r3.y*ga[13]+r3.z*ga[14]+r3.w*ga[15];
            m1 += r4.x*ga[0]+r4.y*ga[1]+r4.z*ga[2]+r4.w*ga[3]
                + r5.x*ga[4]+r5.y*ga[5]+r5.z*ga[6]+r5.w*ga[7]
                + r6.x*ga[8]+r6.y*ga[9]+r6.z*ga[10]+r6.w*ga[11]
                + r7.x*ga[12]+r7.y*ga[13]+r7.z*ga[14]+r7.w*ga[15];
            m2 += r8.x*ga[0]+r8.y*ga[1]+r8.z*ga[2]+r8.w*ga[3]
                + r9.x*ga[4]+r9.y*ga[5]+r9.z*ga[6]+r9.w*ga[7]
                + rA.x*ga[8]+rA.y*ga[9]+rA.z*ga[10]+rA.w*ga[11]
                + rB.x*ga[12]+rB.y*ga[13]+rB.z*ga[14]+rB.w*ga[15];
            m3 += rC.x*ga[0]+rC.y*ga[1]+rC.z*ga[2]+rC.w*ga[3]
                + rD.x*ga[4]+rD.y*ga[5]+rD.z*ga[6]+rD.w*ga[7]
                + rE.x*ga[8]+rE.y*ga[9]+rE.z*ga[10]+rE.w*ga[11]
                + rF.x*ga[12]+rF.y*ga[13]+rF.z*ga[14]+rF.w*ga[15];

            atomicAdd(&g_acc[(size_t)d0 * D + o], (unsigned long long)(long long)llrintf(m0 * FP_SCALE));
            atomicAdd(&g_acc[(size_t)d1 * D + o], (unsigned long long)(long long)llrintf(m1 * FP_SCALE));
            atomicAdd(&g_acc[(size_t)d2 * D + o], (unsigned long long)(long long)llrintf(m2 * FP_SCALE));
            atomicAdd(&g_acc[(size_t)d3 * D + o], (unsigned long long)(long long)llrintf(m3 * FP_SCALE));
        }
        for (; ps < end; ps++) {
            const float4* he4 = (const float4*)(g_he_s + (size_t)ps * D);
            float4 h0 = he4[0], h1 = he4[1], h2 = he4[2], h3 = he4[3];
            float m = btv;
            m += h0.x*ga[0]  + h0.y*ga[1]  + h0.z*ga[2]  + h0.w*ga[3];
            m += h1.x*ga[4]  + h1.y*ga[5]  + h1.z*ga[6]  + h1.w*ga[7];
            m += h2.x*ga[8]  + h2.y*ga[9]  + h2.z*ga[10] + h2.w*ga[11];
            m += h3.x*ga[12] + h3.y*ga[13] + h3.z*ga[14] + h3.w*ga[15];
            atomicAdd(&g_acc[(size_t)g_dn[ps] * D + o], (unsigned long long)(long long)llrintf(m * FP_SCALE));
        }
    }
}

// ---------------- K_agg: elementwise aggregate + root + BN stats -------------
__global__ void K_agg(const float* __restrict__ h_in,
                      const float* __restrict__ root,
                      const float* __restrict__ conv_bias,
                      int layer, int N) {
    __shared__ float s_root[D * D];
    __shared__ float s_bias[D];
    __shared__ unsigned long long s_sum[D];
    __shared__ unsigned long long s_sq[D];
    int tid = threadIdx.x;
    if (tid < D * D) s_root[tid] = root[layer * D * D + tid];
    if (tid < D)     s_bias[tid] = conv_bias[layer * D + tid];
    if (tid < D)     { s_sum[tid] = 0ull; s_sq[tid] = 0ull; }
    __syncthreads();

    int gi = blockIdx.x * blockDim.x + tid;
    int o = gi & 15, n = gi >> 4;

    if (n < N) {
        long long acc = (long long)g_acc[gi];
        g_acc[gi] = 0ull;                        // re-arm (keeps acc zero at entry)
        // exact hi/lo split: value = hi + lo * 2^-32 (no FP64)
        float aggv = (float)(int)(acc >> 32) + (float)(unsigned)acc * FP_INVF;
        int deg = g_z.deg[1][n];
        if (deg == 0) deg = 1;
        aggv = __fdividef(aggv, (float)deg);

        float hv[D];
        const float4* h4 = (const float4*)(h_in + (size_t)n * D);
        float4 v4;
        v4 = h4[0]; hv[0]=v4.x; hv[1]=v4.y; hv[2]=v4.z; hv[3]=v4.w;
        v4 = h4[1]; hv[4]=v4.x; hv[5]=v4.y; hv[6]=v4.z; hv[7]=v4.w;
        v4 = h4[2]; hv[8]=v4.x; hv[9]=v4.y; hv[10]=v4.z; hv[11]=v4.w;
        v4 = h4[3]; hv[12]=v4.x; hv[13]=v4.y; hv[14]=v4.z; hv[15]=v4.w;

        float hs = aggv + s_bias[o];
#pragma unroll
        for (int i = 0; i < D; i++) hs += hv[i] * s_root[i * D + o];

        g_hpre[gi] = hs;
        atomicAdd(&s_sum[o], (unsigned long long)(long long)llrintf(hs * FP_SCALE));
        atomicAdd(&s_sq[o],  (unsigned long long)(long long)llrintf(hs * hs * FP_SCALE));
    }
    __syncthreads();
    if (tid < D) {
        atomicAdd(&g_bnsum[tid],     s_sum[tid]);
        atomicAdd(&g_bnsum[D + tid], s_sq[tid]);
    }
}

// ---------------- K_bnact: batchnorm + tanh (coeffs hoisted to preamble) -----
__global__ void K_bnact(const float* __restrict__ gamma,
                        const float* __restrict__ beta,
                        float* __restrict__ h_out,
                        int layer, int N) {
    __shared__ float s_sc[D], s_sh[D];
    int tid = threadIdx.x;
    if (tid < D) {
        double sum = (double)(long long)g_bnsum[tid]     * FP_INV;
        double sq  = (double)(long long)g_bnsum[D + tid] * FP_INV;
        double inv = 1.0 / (double)N;
        double mu  = sum * inv;
        double var = sq * inv - mu * mu;
        float sc = gamma[layer * D + tid] * rsqrtf((float)(var + 1e-5));
        s_sc[tid] = sc;
        s_sh[tid] = beta[layer * D + tid] - (float)mu * sc;
    }
    __syncthreads();
    int gi = blockIdx.x * blockDim.x + tid;
    if (gi >= N * D) return;
    int o = gi & 15;
    h_out[gi] = ftanh(g_hpre[gi] * s_sc[o] + s_sh[o]);
}

// ---------------- K_poolfc: pooling + readout MLP + log_softmax --------------
__global__ void K_poolfc(const float* __restrict__ hid,
                         const int*   __restrict__ lengths,
                         const float* __restrict__ fc1_w, const float* __restrict__ fc1_b,
                         const float* __restrict__ fc2_w, const float* __restrict__ fc2_b,
                         float* __restrict__ pooled, float* __restrict__ fc_out,
                         float* __restrict__ ls_out, int N, int G) {
    int g = blockIdx.x, t = threadIdx.x;   // 128 threads
    __shared__ float shs[128], shx[128], shn[128];
    __shared__ int swi[4];
    __shared__ int s_nb;
    __shared__ float sp[64], st16[16], sfc[16];
    __shared__ float s_lse;

    int acc = 0;
    for (int i = t; i < g; i += 128) acc += lengths[i];
#pragma unroll
    for (int off = 16; off; off >>= 1) acc += __shfl_down_sync(0xffffffffu, acc, off);
    if ((t & 31) == 0) swi[t >> 5] = acc;
    __syncthreads();
    if (t == 0) s_nb = swi[0] + swi[1] + swi[2] + swi[3];
    __syncthreads();
    int nb = s_nb;
    int len = lengths[g];
    int ne = min(N, nb + len);

    int c = t & 15, r = t >> 4;
    float s = 0.f, mx = -3.402823e38f, mn = 3.402823e38f;
    for (int i = nb + r; i < ne; i += 8) {
        float v = hid[i * D + c];
        s += v; mx = fmaxf(mx, v); mn = fminf(mn, v);
    }
    shs[t] = s; shx[t] = mx; shn[t] = mn;
    __syncthreads();
    for (int off = 64; off >= 16; off >>= 1) {
        if (t < off) {
            shs[t] += shs[t + off];
            shx[t] = fmaxf(shx[t], shx[t + off]);
            shn[t] = fminf(shn[t], shn[t + off]);
        }
        __syncthreads();
    }
    if (t < D) {
        float cnt = fmaxf((float)len, 1.f);
        float ssum = shs[t];
        sp[t]      = __fdividef(ssum, cnt);
        sp[16 + t] = shx[t];
        sp[32 + t] = shn[t];
        sp[48 + t] = ssum;
        pooled[g * 64 + t]      = sp[t];
        pooled[g * 64 + 16 + t] = shx[t];
        pooled[g * 64 + 32 + t] = shn[t];
        pooled[g * 64 + 48 + t] = ssum;
    }
    __syncthreads();
    if (t < 16) {
        float a = fc1_b[t];
#pragma unroll
        for (int k = 0; k < 64; k++) a += sp[k] * fc1_w[k * 16 + t];
        st16[t] = ftanh(a);
    }
    __syncthreads();
    if (t < 10) {
        float a = fc2_b[t];
#pragma unroll
        for (int k = 0; k < 16; k++) a += st16[k] * fc2_w[k * 10 + t];
        sfc[t] = a;
        fc_out[g * 10 + t] = a;
    }
    __syncthreads();
    if (t == 0) {
        float m = sfc[0];
        for (int k = 1; k < 10; k++) m = fmaxf(m, sfc[k]);
        float se = 0.f;
        for (int k = 0; k < 10; k++) se += __expf(sfc[k] - m);
        s_lse = __logf(se) + m;
    }
    __syncthreads();
    if (t < 10) ls_out[g * 10 + t] = sfc[t] - s_lse;
}

// =============================== host launcher =================================
extern "C" void kernel_launch(void* const* d_in, const int* in_sizes, int n_in,
                              void* d_out, int out_size) {
    const float* x         = (const float*)d_in[0];
    const float* edge_attr = (const float*)d_in[1];
    const float* edge_w1   = (const float*)d_in[2];
    const float* edge_b1   = (const float*)d_in[3];
    const float* edge_w2   = (const float*)d_in[4];
    const float* edge_b2   = (const float*)d_in[5];
    const float* root      = (const float*)d_in[6];
    const float* conv_bias = (const float*)d_in[7];
    const float* bn_gamma  = (const float*)d_in[8];
    const float* bn_beta   = (const float*)d_in[9];
    const float* fc1_w     = (const float*)d_in[10];
    const float* fc1_b     = (const float*)d_in[11];
    const float* fc2_w     = (const float*)d_in[12];
    const float* fc2_b     = (const float*)d_in[13];
    const int*   edge_index= (const int*)d_in[14];
    const int*   lengths   = (const int*)d_in[15];

    int N = in_sizes[0] / D;
    int E = in_sizes[1] / EF;
    int G = in_sizes[15];

    float* out        = (float*)d_out;
    float* out_hidden = out;
    float* out_pooled = out + (size_t)N * D;
    float* out_fc     = out_pooled + (size_t)G * 64;
    float* out_ls     = out_fc + (size_t)G * 10;

    // ---- setup: small memset (deg+cur only), degrees, fused scan, edge fill --
    void* zp = 0;
    cudaGetSymbolAddress(&zp, g_z);
    cudaMemsetAsync(zp, 0, sizeof(ZeroBlk));

    K_deg <<<(E + 255) / 256, 256>>>(edge_index, E);
    K_s1  <<<SCB, 256>>>(N);
    K_s3  <<<SCB, 256>>>(N);
    K_edgefill<<<(E + 127) / 128, 128>>>(edge_attr, edge_w1, edge_b1, edge_index, E);

    int nodeBlocks = (N + 15) / 16;
    int elemBlocks = (N * D + 255) / 256;
    int gmsgGrid = GMSG_BLOCKS < nodeBlocks ? GMSG_BLOCKS : nodeBlocks;

    // ---- layers ----
    for (int l = 0; l < NLAYERS; l++) {
        const float* h_in = (l == 0) ? x : g_hbuf;
        float* h_out = (l == NLAYERS - 1) ? out_hidden : g_hbuf;
        K_gmsg <<<gmsgGrid, 256>>>(h_in, edge_w2, edge_b2, N, nodeBlocks);
        K_agg  <<<elemBlocks, 256>>>(h_in, root, conv_bias, l, N);
        K_bnact<<<elemBlocks, 256>>>(bn_gamma, bn_beta, h_out, l, N);
    }

    // ---- pooling + readout ----
    K_poolfc<<<G, 128>>>(out_hidden, lengths, fc1_w, fc1_b, fc2_w, fc2_b,
                         out_pooled, out_fc, out_ls, N, G);
}

// round 17
// speedup vs baseline: 1.0725x; 1.0064x over previous
#include <cuda_runtime.h>
#include <math.h>

#define D 16
#define EF 8
#define NLAYERS 3
#define MAX_N 50048
#define MAX_E 500224
#define SCB 128
#define FP_SCALE 4294967296.0f
#define FP_INVF 2.3283064365386963e-10f
#define FP_INV 2.3283064365386963e-10
#define GMSG_BLOCKS 740              // persistent grid: 5 blocks x 148 SMs

// ---------------- static device scratch ----------------
struct ZeroBlk {                             // zeroed by ONE small cudaMemsetAsync
    int deg[2][MAX_N];                       // 0=src deg, 1=dst deg
    int cur[MAX_N];                          // src-CSR fill cursor
};
__device__ ZeroBlk g_z;

// acc is NOT in the memset: zero-initialized at module load, and K_agg re-arms
// every word to 0 after reading it, so it is zero at entry of every launch.
__device__ unsigned long long g_acc[MAX_N * D];

__device__ float g_he_s[MAX_E * D];          // edge MLP output, src-CSR order
__device__ int   g_dn  [MAX_E];              // src-slot -> dst NODE id
__device__ int   g_off [MAX_N + 1];          // src-CSR offsets (monotonic)
__device__ int   g_part[SCB];                // scan partials
__device__ float g_hbuf[MAX_N * D];          // activated features (layer input)
__device__ float g_hpre[MAX_N * D];          // pre-BN activations
__device__ unsigned long long g_bnsum[32];   // fixed-point BN sum / sumsq

// fast tanh (EX2 + fast divide), err ~1e-7
__device__ __forceinline__ float ftanh(float x) {
    x = fminf(fmaxf(x, -15.f), 15.f);
    float e = __expf(2.f * x);
    return __fdividef(e - 1.f, e + 1.f);
}

// block exclusive scan of one int per thread; total left in s_w[32]
__device__ __forceinline__ int blk_ex_scan(int v, int* s_w) {
    int tid = threadIdx.x, lane = tid & 31, wid = tid >> 5;
    int nw = blockDim.x >> 5;
    int x = v;
#pragma unroll
    for (int d = 1; d < 32; d <<= 1) {
        int y = __shfl_up_sync(0xffffffffu, x, d);
        if (lane >= d) x += y;
    }
    if (lane == 31) s_w[wid] = x;
    __syncthreads();
    if (wid == 0) {
        int w = (lane < nw) ? s_w[lane] : 0;
        int xw = w;
#pragma unroll
        for (int d = 1; d < 32; d <<= 1) {
            int y = __shfl_up_sync(0xffffffffu, xw, d);
            if (lane >= d) xw += y;
        }
        if (lane < nw) s_w[lane] = xw - w;
        if (lane == 31) s_w[32] = xw;
    }
    __syncthreads();
    return s_w[wid] + (x - v);
}

// ---------------- K_deg ----------------
__global__ void K_deg(const int* __restrict__ ei, int E) {
    int e = blockIdx.x * blockDim.x + threadIdx.x;
    if (e >= E) return;
    atomicAdd(&g_z.deg[0][ei[e]], 1);
    atomicAdd(&g_z.deg[1][ei[E + e]], 1);
}

// ---------------- K_s1: per-block partial sums over src degrees --------------
__global__ void K_s1(int n) {
    int chunk = (n + SCB - 1) / SCB;
    int beg = blockIdx.x * chunk;
    int end = min(n, beg + chunk);
    int s = 0;
    for (int i = beg + threadIdx.x; i < end; i += blockDim.x) s += g_z.deg[0][i];
    __shared__ int sw[8];
    int lane = threadIdx.x & 31, wid = threadIdx.x >> 5;
#pragma unroll
    for (int o = 16; o; o >>= 1) s += __shfl_down_sync(0xffffffffu, s, o);
    if (lane == 0) sw[wid] = s;
    __syncthreads();
    if (threadIdx.x == 0) {
        int t = 0;
        for (int w = 0; w < (int)(blockDim.x >> 5); w++) t += sw[w];
        g_part[blockIdx.x] = t;
    }
}

// ---------------- K_s3: fused partial-scan + apply ----------------
__global__ void K_s3(int n) {
    __shared__ int s_w[33];
    __shared__ int sred[8];
    __shared__ int s_base;
    {
        int v = (threadIdx.x < SCB && threadIdx.x < (int)blockIdx.x) ? g_part[threadIdx.x] : 0;
        int lane = threadIdx.x & 31, wid = threadIdx.x >> 5;
#pragma unroll
        for (int d2 = 16; d2; d2 >>= 1) v += __shfl_down_sync(0xffffffffu, v, d2);
        if (lane == 0) sred[wid] = v;
        __syncthreads();
        if (threadIdx.x == 0) {
            int t = 0;
            for (int w = 0; w < 8; w++) t += sred[w];
            s_base = t;
        }
        __syncthreads();
    }
    int chunk = (n + SCB - 1) / SCB;
    int beg = blockIdx.x * chunk;
    int end = min(n, beg + chunk);
    int base = s_base;
    for (int t0 = beg; t0 < end; t0 += blockDim.x) {
        int i = t0 + threadIdx.x;
        int v = (i < end) ? g_z.deg[0][i] : 0;
        int ex = blk_ex_scan(v, s_w);
        int tot = s_w[32];
        __syncthreads();
        if (i < end) g_off[i] = base + ex;
        base += tot;
    }
    if (blockIdx.x == SCB - 1 && threadIdx.x == 0) g_off[n] = base;
}

// ---------------- K_edgefill: edge MLP -> src-CSR slot + dst node id ---------
__global__ void K_edgefill(const float* __restrict__ edge_attr,
                           const float* __restrict__ w1,
                           const float* __restrict__ b1,
                           const int*   __restrict__ ei, int E) {
    __shared__ float s_w1[EF * D];
    __shared__ float s_b1[D];
    int tid = threadIdx.x;
    if (tid < EF * D) s_w1[tid] = w1[tid];
    if (tid < D)      s_b1[tid] = b1[tid];
    __syncthreads();

    int e = blockIdx.x * blockDim.x + tid;
    if (e >= E) return;

    const float4* ea = (const float4*)(edge_attr + (size_t)e * EF);
    float4 a0 = ea[0], a1 = ea[1];
    float a[8] = {a0.x, a0.y, a0.z, a0.w, a1.x, a1.y, a1.z, a1.w};

    float out[D];
#pragma unroll
    for (int j = 0; j < D; j++) {
        float acc = s_b1[j];
#pragma unroll
        for (int k = 0; k < EF; k++) acc += a[k] * s_w1[k * D + j];
        out[j] = ftanh(acc);
    }

    int s = ei[e];
    int d = ei[E + e];
    int ps = g_off[s] + atomicAdd(&g_z.cur[s], 1);
    g_dn[ps] = d;
    float4* dst4 = (float4*)(g_he_s + (size_t)ps * D);
    dst4[0] = make_float4(out[0], out[1], out[2], out[3]);
    dst4[1] = make_float4(out[4], out[5], out[6], out[7]);
    dst4[2] = make_float4(out[8], out[9], out[10], out[11]);
    dst4[3] = make_float4(out[12], out[13], out[14], out[15]);
}

// ---------------- K_gmsg: persistent fused transform + message scatter -------
// Half-warp per node, lane o. Transform in registers; messages REDG.64'd into
// g_acc (order-invariant int64 fixed point). Grid-stride over node blocks.
__global__ void __launch_bounds__(256) K_gmsg(const float* __restrict__ h_in,
                                              const float* __restrict__ w2,
                                              const float* __restrict__ b2,
                                              int N, int nodeBlocks) {
    __shared__ float s_w2[D * 256];
    __shared__ float s_b2[256];
    int tid = threadIdx.x;
    for (int i = tid; i < D * 256; i += blockDim.x) s_w2[i] = w2[i];
    for (int i = tid; i < 256; i += blockDim.x)     s_b2[i] = b2[i];
    if (blockIdx.x == 0 && tid < 32) g_bnsum[tid] = 0ull;  // reset BN accum
    __syncthreads();

    int o = tid & 15;

    for (int nb = blockIdx.x; nb < nodeBlocks; nb += gridDim.x) {
        int node = nb * 16 + (tid >> 4);
        if (node >= N) continue;

        float hv[D];
        {
            const float4* h4 = (const float4*)(h_in + (size_t)node * D);
            float4 v;
            v = h4[0]; hv[0]=v.x; hv[1]=v.y; hv[2]=v.z; hv[3]=v.w;
            v = h4[1]; hv[4]=v.x; hv[5]=v.y; hv[6]=v.z; hv[7]=v.w;
            v = h4[2]; hv[8]=v.x; hv[9]=v.y; hv[10]=v.z; hv[11]=v.w;
            v = h4[3]; hv[12]=v.x; hv[13]=v.y; hv[14]=v.z; hv[15]=v.w;
        }

        float ga[D];
#pragma unroll
        for (int j = 0; j < D; j++) ga[j] = 0.f;
        float btv = 0.f;
#pragma unroll
        for (int i = 0; i < D; i++) {
            float h = hv[i];
            int base = i * D + o;
#pragma unroll
            for (int j = 0; j < D; j++) ga[j] += h * s_w2[j * 256 + base];
            btv += h * s_b2[base];
        }

        int beg = g_off[node];
        int end = g_off[node + 1];
        int ps = beg;
        for (; ps + 4 <= end; ps += 4) {
            const float4* b4 = (const float4*)(g_he_s + (size_t)ps * D);
            float4 r0 = b4[0],  r1 = b4[1],  r2 = b4[2],  r3 = b4[3];
            float4 r4 = b4[4],  r5 = b4[5],  r6 = b4[6],  r7 = b4[7];
            float4 r8 = b4[8],  r9 = b4[9],  rA = b4[10], rB = b4[11];
            float4 rC = b4[12], rD = b4[13], rE = b4[14], rF = b4[15];
            int d0 = g_dn[ps], d1 = g_dn[ps+1], d2 = g_dn[ps+2], d3 = g_dn[ps+3];

            float m0 = btv, m1 = btv, m2 = btv, m3 = btv;
            m0 += r0.x*ga[0]+r0.y*ga[1]+r0.z*ga[2]+r0.w*ga[3]
                + r1.x*ga[4]+r1.y*ga[5]+r1.z*ga[6]+r1.w*ga[7]
                + r2.x*ga[8]+r2.y*ga[9]+r2.z*ga[10]+r2.w*ga[11]
                + r3.x*ga[12]+r3.y*ga[13]+r3.z*ga[14]+r3.w*ga[15];
            m1 += r4.x*ga[0]+r4.y*ga[1]+r4.z*ga[2]+r4.w*ga[3]
                + r5.x*ga[4]+r5.y*ga[5]+r5.z*ga[6]+r5.w*ga[7]
                + r6.x*ga[8]+r6.y*ga[9]+r6.z*ga[10]+r6.w*ga[11]
                + r7.x*ga[12]+r7.y*ga[13]+r7.z*ga[14]+r7.w*ga[15];
            m2 += r8.x*ga[0]+r8.y*ga[1]+r8.z*ga[2]+r8.w*ga[3]
                + r9.x*ga[4]+r9.y*ga[5]+r9.z*ga[6]+r9.w*ga[7]
                + rA.x*ga[8]+rA.y*ga[9]+rA.z*ga[10]+rA.w*ga[11]
                + rB.x*ga[12]+rB.y*ga[13]+rB.z*ga[14]+rB.w*ga[15];
            m3 += rC.x*ga[0]+rC.y*ga[1]+rC.z*ga[2]+rC.w*ga[3]
                + rD.x*ga[4]+rD.y*ga[5]+rD.z*ga[6]+rD.w*ga[7]
                + rE.x*ga[8]+rE.y*ga[9]+rE.z*ga[10]+rE.w*ga[11]
                + rF.x*ga[12]+rF.y*ga[13]+rF.z*ga[14]+rF.w*ga[15];

            atomicAdd(&g_acc[(size_t)d0 * D + o], (unsigned long long)(long long)llrintf(m0 * FP_SCALE));
            atomicAdd(&g_acc[(size_t)d1 * D + o], (unsigned long long)(long long)llrintf(m1 * FP_SCALE));
            atomicAdd(&g_acc[(size_t)d2 * D + o], (unsigned long long)(long long)llrintf(m2 * FP_SCALE));
            atomicAdd(&g_acc[(size_t)d3 * D + o], (unsigned long long)(long long)llrintf(m3 * FP_SCALE));
        }
        for (; ps < end; ps++) {
            const float4* he4 = (const float4*)(g_he_s + (size_t)ps * D);
            float4 h0 = he4[0], h1 = he4[1], h2 = he4[2], h3 = he4[3];
            float m = btv;
            m += h0.x*ga[0]  + h0.y*ga[1]  + h0.z*ga[2]  + h0.w*ga[3];
            m += h1.x*ga[4]  + h1.y*ga[5]  + h1.z*ga[6]  + h1.w*ga[7];
            m += h2.x*ga[8]  + h2.y*ga[9]  + h2.z*ga[10] + h2.w*ga[11];
            m += h3.x*ga[12] + h3.y*ga[13] + h3.z*ga[14] + h3.w*ga[15];
            atomicAdd(&g_acc[(size_t)g_dn[ps] * D + o], (unsigned long long)(long long)llrintf(m * FP_SCALE));
        }
    }
}

// ---------------- K_agg: elementwise aggregate + root + BN stats -------------
__global__ void K_agg(const float* __restrict__ h_in,
                      const float* __restrict__ root,
                      const float* __restrict__ conv_bias,
                      int layer, int N) {
    __shared__ float s_root[D * D];
    __shared__ float s_bias[D];
    __shared__ unsigned long long s_sum[D];
    __shared__ unsigned long long s_sq[D];
    int tid = threadIdx.x;
    if (tid < D * D) s_root[tid] = root[layer * D * D + tid];
    if (tid < D)     s_bias[tid] = conv_bias[layer * D + tid];
    if (tid < D)     { s_sum[tid] = 0ull; s_sq[tid] = 0ull; }
    __syncthreads();

    int gi = blockIdx.x * blockDim.x + tid;
    int o = gi & 15, n = gi >> 4;

    if (n < N) {
        long long acc = (long long)g_acc[gi];
        g_acc[gi] = 0ull;                        // re-arm (keeps acc zero at entry)
        // exact hi/lo split: value = hi + lo * 2^-32 (no FP64)
        float aggv = (float)(int)(acc >> 32) + (float)(unsigned)acc * FP_INVF;
        int deg = g_z.deg[1][n];
        if (deg == 0) deg = 1;
        aggv = __fdividef(aggv, (float)deg);

        float hv[D];
        const float4* h4 = (const float4*)(h_in + (size_t)n * D);
        float4 v4;
        v4 = h4[0]; hv[0]=v4.x; hv[1]=v4.y; hv[2]=v4.z; hv[3]=v4.w;
        v4 = h4[1]; hv[4]=v4.x; hv[5]=v4.y; hv[6]=v4.z; hv[7]=v4.w;
        v4 = h4[2]; hv[8]=v4.x; hv[9]=v4.y; hv[10]=v4.z; hv[11]=v4.w;
        v4 = h4[3]; hv[12]=v4.x; hv[13]=v4.y; hv[14]=v4.z; hv[15]=v4.w;

        float hs = aggv + s_bias[o];
#pragma unroll
        for (int i = 0; i < D; i++) hs += hv[i] * s_root[i * D + o];

        g_hpre[gi] = hs;
        atomicAdd(&s_sum[o], (unsigned long long)(long long)llrintf(hs * FP_SCALE));
        atomicAdd(&s_sq[o],  (unsigned long long)(long long)llrintf(hs * hs * FP_SCALE));
    }
    __syncthreads();
    if (tid < D) {
        atomicAdd(&g_bnsum[tid],     s_sum[tid]);
        atomicAdd(&g_bnsum[D + tid], s_sq[tid]);
    }
}

// ---------------- K_bnact: batchnorm + tanh (layers 0..NLAYERS-2 only) -------
__global__ void K_bnact(const float* __restrict__ gamma,
                        const float* __restrict__ beta,
                        float* __restrict__ h_out,
                        int layer, int N) {
    __shared__ float s_sc[D], s_sh[D];
    int tid = threadIdx.x;
    if (tid < D) {
        double sum = (double)(long long)g_bnsum[tid]     * FP_INV;
        double sq  = (double)(long long)g_bnsum[D + tid] * FP_INV;
        double inv = 1.0 / (double)N;
        double mu  = sum * inv;
        double var = sq * inv - mu * mu;
        float sc = gamma[layer * D + tid] * rsqrtf((float)(var + 1e-5));
        s_sc[tid] = sc;
        s_sh[tid] = beta[layer * D + tid] - (float)mu * sc;
    }
    __syncthreads();
    int gi = blockIdx.x * blockDim.x + tid;
    if (gi >= N * D) return;
    int o = gi & 15;
    h_out[gi] = ftanh(g_hpre[gi] * s_sc[o] + s_sh[o]);
}

// ---------------- K_poolfc: final BN+tanh + hidden out + pooling + MLP -------
// (numerically validated in R15)
__global__ void K_poolfc(const int*   __restrict__ lengths,
                         const float* __restrict__ gamma, const float* __restrict__ beta,
                         const float* __restrict__ fc1_w, const float* __restrict__ fc1_b,
                         const float* __restrict__ fc2_w, const float* __restrict__ fc2_b,
                         float* __restrict__ hidden_out, float* __restrict__ pooled,
                         float* __restrict__ fc_out, float* __restrict__ ls_out,
                         int N, int G) {
    int g = blockIdx.x, t = threadIdx.x;   // 128 threads
    __shared__ float shs[128], shx[128], shn[128];
    __shared__ int swi[4];
    __shared__ int s_nb;
    __shared__ float sp[64], st16[16], sfc[16];
    __shared__ float s_lse;
    __shared__ float s_sc[D], s_sh[D];

    // BN coefficients for the final layer (g_bnsum complete: stream-ordered)
    if (t < D) {
        double sum = (double)(long long)g_bnsum[t]     * FP_INV;
        double sq  = (double)(long long)g_bnsum[D + t] * FP_INV;
        double inv = 1.0 / (double)N;
        double mu  = sum * inv;
        double var = sq * inv - mu * mu;
        float sc = gamma[(NLAYERS - 1) * D + t] * rsqrtf((float)(var + 1e-5));
        s_sc[t] = sc;
        s_sh[t] = beta[(NLAYERS - 1) * D + t] - (float)mu * sc;
    }

    int acc = 0;
    for (int i = t; i < g; i += 128) acc += lengths[i];
#pragma unroll
    for (int off = 16; off; off >>= 1) acc += __shfl_down_sync(0xffffffffu, acc, off);
    if ((t & 31) == 0) swi[t >> 5] = acc;
    __syncthreads();
    if (t == 0) s_nb = swi[0] + swi[1] + swi[2] + swi[3];
    __syncthreads();
    int nb = s_nb;
    int len = lengths[g];
    int ne = min(N, nb + len);

    int c = t & 15, r = t >> 4;
    float scl = s_sc[c], shf = s_sh[c];
    float s = 0.f, mx = -3.402823e38f, mn = 3.402823e38f;
    for (int i = nb + r; i < ne; i += 8) {
        float v = ftanh(g_hpre[i * D + c] * scl + shf);
        hidden_out[i * D + c] = v;
        s += v; mx = fmaxf(mx, v); mn = fminf(mn, v);
    }
    shs[t] = s; shx[t] = mx; shn[t] = mn;
    __syncthreads();
    for (int off = 64; off >= 16; off >>= 1) {
        if (t < off) {
            shs[t] += shs[t + off];
            shx[t] = fmaxf(shx[t], shx[t + off]);
            shn[t] = fminf(shn[t], shn[t + off]);
        }
        __syncthreads();
    }
    if (t < D) {
        float cnt = fmaxf((float)len, 1.f);
        float ssum = shs[t];
        sp[t]      = __fdividef(ssum, cnt);
        sp[16 + t] = shx[t];
        sp[32 + t] = shn[t];
        sp[48 + t] = ssum;
        pooled[g * 64 + t]      = sp[t];
        pooled[g * 64 + 16 + t] = shx[t];
        pooled[g * 64 + 32 + t] = shn[t];
        pooled[g * 64 + 48 + t] = ssum;
    }
    __syncthreads();
    if (t < 16) {
        float a = fc1_b[t];
#pragma unroll
        for (int k = 0; k < 64; k++) a += sp[k] * fc1_w[k * 16 + t];
        st16[t] = ftanh(a);
    }
    __syncthreads();
    if (t < 10) {
        float a = fc2_b[t];
#pragma unroll
        for (int k = 0; k < 16; k++) a += st16[k] * fc2_w[k * 10 + t];
        sfc[t] = a;
        fc_out[g * 10 + t] = a;
    }
    __syncthreads();
    if (t == 0) {
        float m = sfc[0];
        for (int k = 1; k < 10; k++) m = fmaxf(m, sfc[k]);
        float se = 0.f;
        for (int k = 0; k < 10; k++) se += __expf(sfc[k] - m);
        s_lse = __logf(se) + m;
    }
    __syncthreads();
    if (t < 10) ls_out[g * 10 + t] = sfc[t] - s_lse;
}

// =============================== host launcher =================================
extern "C" void kernel_launch(void* const* d_in, const int* in_sizes, int n_in,
                              void* d_out, int out_size) {
    const float* x         = (const float*)d_in[0];
    const float* edge_attr = (const float*)d_in[1];
    const float* edge_w1   = (const float*)d_in[2];
    const float* edge_b1   = (const float*)d_in[3];
    const float* edge_w2   = (const float*)d_in[4];
    const float* edge_b2   = (const float*)d_in[5];
    const float* root      = (const float*)d_in[6];
    const float* conv_bias = (const float*)d_in[7];
    const float* bn_gamma  = (const float*)d_in[8];
    const float* bn_beta   = (const float*)d_in[9];
    const float* fc1_w     = (const float*)d_in[10];
    const float* fc1_b     = (const float*)d_in[11];
    const float* fc2_w     = (const float*)d_in[12];
    const float* fc2_b     = (const float*)d_in[13];
    const int*   edge_index= (const int*)d_in[14];
    const int*   lengths   = (const int*)d_in[15];

    int N = in_sizes[0] / D;
    int E = in_sizes[1] / EF;
    int G = in_sizes[15];

    float* out        = (float*)d_out;
    float* out_hidden = out;
    float* out_pooled = out + (size_t)N * D;
    float* out_fc     = out_pooled + (size_t)G * 64;
    float* out_ls     = out_fc + (size_t)G * 10;

    // ---- setup: small memset (deg+cur only), degrees, fused scan, edge fill --
    void* zp = 0;
    cudaGetSymbolAddress(&zp, g_z);
    cudaMemsetAsync(zp, 0, sizeof(ZeroBlk));

    K_deg <<<(E + 255) / 256, 256>>>(edge_index, E);
    K_s1  <<<SCB, 256>>>(N);
    K_s3  <<<SCB, 256>>>(N);
    K_edgefill<<<(E + 127) / 128, 128>>>(edge_attr, edge_w1, edge_b1, edge_index, E);

    int nodeBlocks = (N + 15) / 16;
    int elemBlocks = (N * D + 255) / 256;
    int gmsgGrid = GMSG_BLOCKS < nodeBlocks ? GMSG_BLOCKS : nodeBlocks;

    // ---- layers (final layer's BN+tanh is fused into K_poolfc) ----
    for (int l = 0; l < NLAYERS; l++) {
        const float* h_in = (l == 0) ? x : g_hbuf;
        K_gmsg <<<gmsgGrid, 256>>>(h_in, edge_w2, edge_b2, N, nodeBlocks);
        K_agg  <<<elemBlocks, 256>>>(h_in, root, conv_bias, l, N);
        if (l < NLAYERS - 1)
            K_bnact<<<elemBlocks, 256>>>(bn_gamma, bn_beta, g_hbuf, l, N);
    }

    // ---- final BN + hidden + pooling + readout ----
    K_poolfc<<<G, 128>>>(lengths, bn_gamma, bn_beta, fc1_w, fc1_b, fc2_w, fc2_b,
                         out_hidden, out_pooled, out_fc, out_ls, N, G);
}